// round 6
// baseline (speedup 1.0000x reference)
#include <cuda_runtime.h>
#include <cuda_bf16.h>

// Contamination: out = 0.8*x + 0.2 * avg(valid neighbors at {-8,0,8}^2 \ {0,0})
// x: [B=8, C=32, H=512, W=512] fp32, k=8.
//
// R6 = R5 (97.2us) with two L1-op cuts:
//  - center of current row is carried in the roll (it's last iteration's n1
//    load) -> the per-iteration ctr reload is gone, zero extra liveness.
//  - 8 output rows per thread (tile 128x64) -> prologue amortized 2x.
// L1 ops/output: 6.5 -> 4.75. Same per-iteration miss-MLP (3 batched loads),
// same 32-reg / 8-blocks-per-SM occupancy target.

namespace {

constexpr int H  = 512;
constexpr int W  = 512;
constexpr int K  = 8;
constexpr int W4 = W / 4;       // 128 float4 per row
constexpr int RY = 8;           // output rows per thread

__device__ __forceinline__ float4 f4add(float4 a, float4 b) {
    return make_float4(a.x + b.x, a.y + b.y, a.z + b.z, a.w + b.w);
}

__global__ __launch_bounds__(256, 8)
void contam_kernel(const float4* __restrict__ in, float4* __restrict__ out) {
    const int c4   = blockIdx.x * 32 + threadIdx.x;    // float4 column, 0..127
    const int row0 = blockIdx.y * 64 + threadIdx.y;    // first output row
    const long plane = blockIdx.z;

    const float4* __restrict__ pin  = in  + plane * (long)(H * W4);
    float4* __restrict__       pout = out + plane * (long)(H * W4);

    const bool hasL = (c4 >= 2);
    const bool hasR = (c4 <= W4 - 3);
    const int  nc   = 1 + (int)hasL + (int)hasR;

    // ---- prologue: rows row0-8 (sum only) and row0 (sum + center) ----
    float4 Sprev = make_float4(0.f, 0.f, 0.f, 0.f);
    if (row0 >= K) {
        const float4* __restrict__ r = pin + (long)(row0 - K) * W4;
        Sprev = r[c4];
        if (hasL) Sprev = f4add(Sprev, r[c4 - 2]);
        if (hasR) Sprev = f4add(Sprev, r[c4 + 2]);
    }
    float4 Ccur, Scur;
    {
        const float4* __restrict__ r = pin + (long)row0 * W4;
        Ccur = r[c4];
        Scur = Ccur;
        if (hasL) Scur = f4add(Scur, r[c4 - 2]);
        if (hasR) Scur = f4add(Scur, r[c4 + 2]);
    }

    #pragma unroll
    for (int ry = 0; ry < RY; ry++) {
        const int h  = row0 + ry * K;
        const int rn = h + K;
        const bool vn = (rn < H);

        // ---- batched, independent next-row loads ----
        const float4* __restrict__ rowN = pin + (long)(vn ? rn : h) * W4;
        float4 n1 = rowN[c4];
        float4 n0 = hasL ? rowN[c4 - 2] : make_float4(0,0,0,0);
        float4 n2 = hasR ? rowN[c4 + 2] : make_float4(0,0,0,0);

        float4 Snext = vn ? f4add(f4add(n1, n0), n2)
                          : make_float4(0.f, 0.f, 0.f, 0.f);

        const int nr = 1 + (int)(h >= K) + (int)vn;
        // count = nr*nc - 1 in {3,5,8}  <=>  nr+nc in {4,5,6}
        const int s  = nr + nc;
        const float scale = (s == 6) ? 0.025f
                          : (s == 5) ? 0.04f
                                     : 0.066666667f;
        const float a = 0.8f - scale;

        // acc includes the center, so out = (0.8 - scale)*ctr + scale*acc
        float4 acc = f4add(f4add(Sprev, Scur), Snext);

        float4 o;
        o.x = a * Ccur.x + scale * acc.x;
        o.y = a * Ccur.y + scale * acc.y;
        o.z = a * Ccur.z + scale * acc.z;
        o.w = a * Ccur.w + scale * acc.w;

        __stcs(&pout[(long)h * W4 + c4], o);

        Sprev = Scur;
        Scur  = Snext;
        Ccur  = n1;          // next row's center, loaded this iteration
    }
}

} // namespace

extern "C" void kernel_launch(void* const* d_in, const int* in_sizes, int n_in,
                              void* d_out, int out_size) {
    const float4* x = (const float4*)d_in[0];
    float4* out = (float4*)d_out;

    const int planes = in_sizes[0] / (H * W);   // 256

    dim3 block(32, 8, 1);
    dim3 grid(W4 / 32, H / (RY * 8), planes);   // (4, 8, 256)
    contam_kernel<<<grid, block>>>(x, out);
}

// round 7
// speedup vs baseline: 1.0572x; 1.0572x over previous
#include <cuda_runtime.h>
#include <cuda_bf16.h>

// Contamination: out = 0.8*x + 0.2 * avg(valid neighbors at {-8,0,8}^2 \ {0,0})
// x: [B=8, C=32, H=512, W=512] fp32, k=8.
//
// R7 = R5 (97.2us, traffic at compulsory floor, 32-row tiles that fit the
// concurrent L2 footprint) + the zero-cost piece of R6: the current row's
// center is carried in the roll (previous iteration's n1 load), deleting the
// per-iteration ctr reload. L1 ops/output 6.5 -> 5.5. Tile shape, grid, and
// L2 footprint unchanged (R6 showed 64-row tiles blow the L2 capacity line
// and add ~11% DRAM traffic).

namespace {

constexpr int H  = 512;
constexpr int W  = 512;
constexpr int K  = 8;
constexpr int W4 = W / 4;       // 128 float4 per row

__device__ __forceinline__ float4 f4add(float4 a, float4 b) {
    return make_float4(a.x + b.x, a.y + b.y, a.z + b.z, a.w + b.w);
}

__global__ __launch_bounds__(256, 8)
void contam_kernel(const float4* __restrict__ in, float4* __restrict__ out) {
    const int c4   = blockIdx.x * 32 + threadIdx.x;   // float4 column, 0..127
    const int row0 = blockIdx.y * 32 + threadIdx.y;   // first output row
    const long plane = blockIdx.z;

    const float4* __restrict__ pin  = in  + plane * (long)(H * W4);
    float4* __restrict__       pout = out + plane * (long)(H * W4);

    const bool hasL = (c4 >= 2);
    const bool hasR = (c4 <= W4 - 3);
    const int  nc   = 1 + (int)hasL + (int)hasR;

    // ---- prologue: row row0-8 (sum only), row row0 (sum + center) ----
    float4 Sprev = make_float4(0.f, 0.f, 0.f, 0.f);
    if (row0 >= K) {
        const float4* __restrict__ r = pin + (long)(row0 - K) * W4;
        Sprev = r[c4];
        if (hasL) Sprev = f4add(Sprev, r[c4 - 2]);
        if (hasR) Sprev = f4add(Sprev, r[c4 + 2]);
    }
    float4 Ccur, Scur;
    {
        const float4* __restrict__ r = pin + (long)row0 * W4;
        Ccur = r[c4];
        Scur = Ccur;
        if (hasL) Scur = f4add(Scur, r[c4 - 2]);
        if (hasR) Scur = f4add(Scur, r[c4 + 2]);
    }

    #pragma unroll
    for (int ry = 0; ry < 4; ry++) {
        const int h  = row0 + ry * K;
        const int rn = h + K;
        const bool vn = (rn < H);

        // ---- batched, independent next-row loads ----
        const float4* __restrict__ rowN = pin + (long)(vn ? rn : h) * W4;
        float4 n1 = rowN[c4];
        float4 n0 = hasL ? rowN[c4 - 2] : make_float4(0,0,0,0);
        float4 n2 = hasR ? rowN[c4 + 2] : make_float4(0,0,0,0);

        float4 Snext = vn ? f4add(f4add(n1, n0), n2)
                          : make_float4(0.f, 0.f, 0.f, 0.f);

        const int nr = 1 + (int)(h >= K) + (int)vn;
        // count = nr*nc - 1 in {3,5,8}  <=>  nr+nc in {4,5,6}
        const int s  = nr + nc;
        const float scale = (s == 6) ? 0.025f
                          : (s == 5) ? 0.04f
                                     : 0.066666667f;
        const float a = 0.8f - scale;

        // acc includes the center: out = (0.8 - scale)*ctr + scale*acc
        float4 acc = f4add(f4add(Sprev, Scur), Snext);

        float4 o;
        o.x = a * Ccur.x + scale * acc.x;
        o.y = a * Ccur.y + scale * acc.y;
        o.z = a * Ccur.z + scale * acc.z;
        o.w = a * Ccur.w + scale * acc.w;

        __stcs(&pout[(long)h * W4 + c4], o);

        Sprev = Scur;
        Scur  = Snext;
        Ccur  = n1;          // next row's center, already loaded
    }
}

} // namespace

extern "C" void kernel_launch(void* const* d_in, const int* in_sizes, int n_in,
                              void* d_out, int out_size) {
    const float4* x = (const float4*)d_in[0];
    float4* out = (float4*)d_out;

    const int planes = in_sizes[0] / (H * W);   // 256

    dim3 block(32, 8, 1);
    dim3 grid(W4 / 32, H / 32, planes);         // (4, 16, 256)
    contam_kernel<<<grid, block>>>(x, out);
}

// round 8
// speedup vs baseline: 1.1008x; 1.0412x over previous
#include <cuda_runtime.h>
#include <cuda_bf16.h>

// Contamination: out = 0.8*x + 0.2 * avg(valid neighbors at {-8,0,8}^2 \ {0,0})
// x: [B=8, C=32, H=512, W=512] fp32, k=8.
//
// R8 = R5 (97.2us; 32-row tiles, traffic at compulsory floor) + depth-3
// center-load pipeline. Diagnosis: kernel is stall-bound (all pipes <80%,
// issue ~45%); the only per-iteration DRAM miss is the next-row center,
// consumed in the same iteration -> warps eat full DRAM latency serially.
// Fix: carry centers of rows h+K and h+2K in registers; prefetch h+3K each
// iteration (clamped address when OOB, value discarded by the vn select).
// Side loads become L1 hits on lines fetched 1-2 iterations earlier.
// lb(256,6) = 42-reg cap / 48 warps to hold pipeline regs without spills.

namespace {

constexpr int H  = 512;
constexpr int W  = 512;
constexpr int K  = 8;
constexpr int W4 = W / 4;       // 128 float4 per row

__device__ __forceinline__ float4 f4zero() { return make_float4(0.f, 0.f, 0.f, 0.f); }

__device__ __forceinline__ float4 f4add(float4 a, float4 b) {
    return make_float4(a.x + b.x, a.y + b.y, a.z + b.z, a.w + b.w);
}

__global__ __launch_bounds__(256, 6)
void contam_kernel(const float4* __restrict__ in, float4* __restrict__ out) {
    const int c4   = blockIdx.x * 32 + threadIdx.x;   // float4 column, 0..127
    const int row0 = blockIdx.y * 32 + threadIdx.y;   // first output row (<= 487)
    const int plane = blockIdx.z;

    const float4* __restrict__ pin  = in  + (size_t)plane * (H * W4);
    float4* __restrict__       pout = out + (size_t)plane * (H * W4);

    const bool hasL = (c4 >= 2);
    const bool hasR = (c4 <= W4 - 3);
    const int  nc   = 1 + (int)hasL + (int)hasR;

    // ---- prologue ----
    float4 Sprev = f4zero();
    if (row0 >= K) {
        const float4* __restrict__ r = pin + (row0 - K) * W4;
        Sprev = r[c4];
        if (hasL) Sprev = f4add(Sprev, r[c4 - 2]);
        if (hasR) Sprev = f4add(Sprev, r[c4 + 2]);
    }
    float4 Scur;
    {
        const float4* __restrict__ r = pin + row0 * W4;
        Scur = r[c4];
        if (hasL) Scur = f4add(Scur, r[c4 - 2]);
        if (hasR) Scur = f4add(Scur, r[c4 + 2]);
    }
    // center pipeline: rows row0+K (<=495) and row0+2K (<=503) are always valid
    float4 cN  = pin[(row0 + K)     * W4 + c4];
    float4 cN2 = pin[(row0 + 2 * K) * W4 + c4];

    #pragma unroll
    for (int ry = 0; ry < 4; ry++) {
        const int h   = row0 + ry * K;
        const int rn  = h + K;
        const bool vn = (rn < H);
        const int rn3 = h + 3 * K;
        const int rn3c = (rn3 < H) ? rn3 : h;    // clamped: always a legal address

        // ---- batched issue: ctr (L1 hit), sides of row rn (L1 hits on lines
        //      fetched 1 iteration ago), prefetch center of row h+3K (miss) ----
        const float4* __restrict__ rowC = pin + h * W4;
        const float4* __restrict__ rowN = pin + (vn ? rn : h) * W4;
        float4 ctr = rowC[c4];
        float4 s0  = hasL ? rowN[c4 - 2] : f4zero();
        float4 s2  = hasR ? rowN[c4 + 2] : f4zero();
        float4 cN3 = pin[rn3c * W4 + c4];

        float4 Snext = vn ? f4add(f4add(cN, s0), s2) : f4zero();

        const int nr = 1 + (int)(h >= K) + (int)vn;
        // count = nr*nc - 1 in {3,5,8}  <=>  nr+nc in {4,5,6}
        const int s  = nr + nc;
        const float scale = (s == 6) ? 0.025f
                          : (s == 5) ? 0.04f
                                     : 0.066666667f;

        float4 acc = f4add(f4add(Sprev, Scur), Snext);

        float4 o;
        o.x = 0.8f * ctr.x + scale * (acc.x - ctr.x);
        o.y = 0.8f * ctr.y + scale * (acc.y - ctr.y);
        o.z = 0.8f * ctr.z + scale * (acc.z - ctr.z);
        o.w = 0.8f * ctr.w + scale * (acc.w - ctr.w);

        __stcs(&pout[h * W4 + c4], o);

        Sprev = Scur;
        Scur  = Snext;
        cN    = cN2;
        cN2   = cN3;
    }
}

} // namespace

extern "C" void kernel_launch(void* const* d_in, const int* in_sizes, int n_in,
                              void* d_out, int out_size) {
    const float4* x = (const float4*)d_in[0];
    float4* out = (float4*)d_out;

    const int planes = in_sizes[0] / (H * W);   // 256

    dim3 block(32, 8, 1);
    dim3 grid(W4 / 32, H / 32, planes);         // (4, 16, 256)
    contam_kernel<<<grid, block>>>(x, out);
}

// round 9
// speedup vs baseline: 1.1284x; 1.0251x over previous
#include <cuda_runtime.h>
#include <cuda_bf16.h>

// Contamination: out = 0.8*x + 0.2 * avg(valid neighbors at {-8,0,8}^2 \ {0,0})
// x: [B=8, C=32, H=512, W=512] fp32, k=8.
//
// R9 = R8's center-prefetch pipeline at depth 2 (not 3) so the register count
// fits 7 blocks/SM (36-reg cap, 56 warps = 87.5% occ). R8 proved the pipeline
// raises per-warp BW ~30%; R5 proved occupancy ~90% is worth ~6%. This takes
// both: each iteration's one true DRAM miss (center of row h+2K) is issued a
// full loop body before consumption; side loads hit lines prefetched one
// iteration earlier. 32-row tiles keep concurrent L2 footprint under capacity
// (R6 lesson); traffic stays at the compulsory ~500 MB floor.

namespace {

constexpr int H  = 512;
constexpr int W  = 512;
constexpr int K  = 8;
constexpr int W4 = W / 4;       // 128 float4 per row

__device__ __forceinline__ float4 f4zero() { return make_float4(0.f, 0.f, 0.f, 0.f); }

__device__ __forceinline__ float4 f4add(float4 a, float4 b) {
    return make_float4(a.x + b.x, a.y + b.y, a.z + b.z, a.w + b.w);
}

__global__ __launch_bounds__(256, 7)
void contam_kernel(const float4* __restrict__ in, float4* __restrict__ out) {
    const int c4   = blockIdx.x * 32 + threadIdx.x;   // float4 column, 0..127
    const int row0 = blockIdx.y * 32 + threadIdx.y;   // first output row (<=487)
    const int plane = blockIdx.z;

    const float4* __restrict__ pin  = in  + (size_t)plane * (H * W4);
    float4* __restrict__       pout = out + (size_t)plane * (H * W4);

    const bool hasL = (c4 >= 2);
    const bool hasR = (c4 <= W4 - 3);
    const int  nc   = 1 + (int)hasL + (int)hasR;

    // ---- prologue: Sprev (row0-K sum), Scur (row0 sum), cN = center(row0+K) ----
    float4 Sprev = f4zero();
    if (row0 >= K) {
        const float4* __restrict__ r = pin + (row0 - K) * W4;
        Sprev = r[c4];
        if (hasL) Sprev = f4add(Sprev, r[c4 - 2]);
        if (hasR) Sprev = f4add(Sprev, r[c4 + 2]);
    }
    float4 Scur;
    {
        const float4* __restrict__ r = pin + row0 * W4;
        Scur = r[c4];
        if (hasL) Scur = f4add(Scur, r[c4 - 2]);
        if (hasR) Scur = f4add(Scur, r[c4 + 2]);
    }
    float4 cN = pin[(row0 + K) * W4 + c4];   // row0+K <= 495, always valid

    #pragma unroll
    for (int ry = 0; ry < 4; ry++) {
        const int h   = row0 + ry * K;
        const int rn  = h + K;
        const bool vn = (rn < H);
        const int rn2 = h + 2 * K;
        const int rn2c = (rn2 < H) ? rn2 : h;   // clamped legal address

        // ---- batched issue: ctr (L1 hit), sides of row rn (L1 hits on the
        //      line prefetched last iteration), prefetch center of h+2K (miss) ----
        const float4* __restrict__ rowC = pin + h * W4;
        const float4* __restrict__ rowN = pin + (vn ? rn : h) * W4;
        float4 ctr = rowC[c4];
        float4 s0  = hasL ? rowN[c4 - 2] : f4zero();
        float4 s2  = hasR ? rowN[c4 + 2] : f4zero();
        float4 cN2 = pin[rn2c * W4 + c4];

        float4 Snext = vn ? f4add(f4add(cN, s0), s2) : f4zero();

        const int nr = 1 + (int)(h >= K) + (int)vn;
        // count = nr*nc - 1 in {3,5,8}  <=>  nr+nc in {4,5,6}
        const int s  = nr + nc;
        const float scale = (s == 6) ? 0.025f
                          : (s == 5) ? 0.04f
                                     : 0.066666667f;

        float4 acc = f4add(f4add(Sprev, Scur), Snext);

        float4 o;
        o.x = 0.8f * ctr.x + scale * (acc.x - ctr.x);
        o.y = 0.8f * ctr.y + scale * (acc.y - ctr.y);
        o.z = 0.8f * ctr.z + scale * (acc.z - ctr.z);
        o.w = 0.8f * ctr.w + scale * (acc.w - ctr.w);

        __stcs(&pout[h * W4 + c4], o);

        Sprev = Scur;
        Scur  = Snext;
        cN    = cN2;
    }
}

} // namespace

extern "C" void kernel_launch(void* const* d_in, const int* in_sizes, int n_in,
                              void* d_out, int out_size) {
    const float4* x = (const float4*)d_in[0];
    float4* out = (float4*)d_out;

    const int planes = in_sizes[0] / (H * W);   // 256

    dim3 block(32, 8, 1);
    dim3 grid(W4 / 32, H / 32, planes);         // (4, 16, 256)
    contam_kernel<<<grid, block>>>(x, out);
}

// round 10
// speedup vs baseline: 1.1325x; 1.0036x over previous
#include <cuda_runtime.h>
#include <cuda_bf16.h>

// Contamination: out = 0.8*x + 0.2 * avg(valid neighbors at {-8,0,8}^2 \ {0,0})
// x: [B=8, C=32, H=512, W=512] fp32, k=8.
//
// R10 = R9 (96.9us; depth-2 center-prefetch pipeline, 32-row tiles, batched
// loads, streaming stores) with the residency cap lifted lb(256,7)->lb(256,8).
// R9 compiled to 32 regs, so 8 blocks/SM (64 warps) fit; R5 showed this exact
// 7->8 lift was worth ~4%. Single-variable change.

namespace {

constexpr int H  = 512;
constexpr int W  = 512;
constexpr int K  = 8;
constexpr int W4 = W / 4;       // 128 float4 per row

__device__ __forceinline__ float4 f4zero() { return make_float4(0.f, 0.f, 0.f, 0.f); }

__device__ __forceinline__ float4 f4add(float4 a, float4 b) {
    return make_float4(a.x + b.x, a.y + b.y, a.z + b.z, a.w + b.w);
}

__global__ __launch_bounds__(256, 8)
void contam_kernel(const float4* __restrict__ in, float4* __restrict__ out) {
    const int c4   = blockIdx.x * 32 + threadIdx.x;   // float4 column, 0..127
    const int row0 = blockIdx.y * 32 + threadIdx.y;   // first output row (<=487)
    const int plane = blockIdx.z;

    const float4* __restrict__ pin  = in  + (size_t)plane * (H * W4);
    float4* __restrict__       pout = out + (size_t)plane * (H * W4);

    const bool hasL = (c4 >= 2);
    const bool hasR = (c4 <= W4 - 3);
    const int  nc   = 1 + (int)hasL + (int)hasR;

    // ---- prologue: Sprev (row0-K sum), Scur (row0 sum), cN = center(row0+K) ----
    float4 Sprev = f4zero();
    if (row0 >= K) {
        const float4* __restrict__ r = pin + (row0 - K) * W4;
        Sprev = r[c4];
        if (hasL) Sprev = f4add(Sprev, r[c4 - 2]);
        if (hasR) Sprev = f4add(Sprev, r[c4 + 2]);
    }
    float4 Scur;
    {
        const float4* __restrict__ r = pin + row0 * W4;
        Scur = r[c4];
        if (hasL) Scur = f4add(Scur, r[c4 - 2]);
        if (hasR) Scur = f4add(Scur, r[c4 + 2]);
    }
    float4 cN = pin[(row0 + K) * W4 + c4];   // row0+K <= 495, always valid

    #pragma unroll
    for (int ry = 0; ry < 4; ry++) {
        const int h   = row0 + ry * K;
        const int rn  = h + K;
        const bool vn = (rn < H);
        const int rn2 = h + 2 * K;
        const int rn2c = (rn2 < H) ? rn2 : h;   // clamped legal address

        // ---- batched issue: ctr (L1 hit), sides of row rn (L1 hits on the
        //      line prefetched last iteration), prefetch center of h+2K (miss) ----
        const float4* __restrict__ rowC = pin + h * W4;
        const float4* __restrict__ rowN = pin + (vn ? rn : h) * W4;
        float4 ctr = rowC[c4];
        float4 s0  = hasL ? rowN[c4 - 2] : f4zero();
        float4 s2  = hasR ? rowN[c4 + 2] : f4zero();
        float4 cN2 = pin[rn2c * W4 + c4];

        float4 Snext = vn ? f4add(f4add(cN, s0), s2) : f4zero();

        const int nr = 1 + (int)(h >= K) + (int)vn;
        // count = nr*nc - 1 in {3,5,8}  <=>  nr+nc in {4,5,6}
        const int s  = nr + nc;
        const float scale = (s == 6) ? 0.025f
                          : (s == 5) ? 0.04f
                                     : 0.066666667f;

        float4 acc = f4add(f4add(Sprev, Scur), Snext);

        float4 o;
        o.x = 0.8f * ctr.x + scale * (acc.x - ctr.x);
        o.y = 0.8f * ctr.y + scale * (acc.y - ctr.y);
        o.z = 0.8f * ctr.z + scale * (acc.z - ctr.z);
        o.w = 0.8f * ctr.w + scale * (acc.w - ctr.w);

        __stcs(&pout[h * W4 + c4], o);

        Sprev = Scur;
        Scur  = Snext;
        cN    = cN2;
    }
}

} // namespace

extern "C" void kernel_launch(void* const* d_in, const int* in_sizes, int n_in,
                              void* d_out, int out_size) {
    const float4* x = (const float4*)d_in[0];
    float4* out = (float4*)d_out;

    const int planes = in_sizes[0] / (H * W);   // 256

    dim3 block(32, 8, 1);
    dim3 grid(W4 / 32, H / 32, planes);         // (4, 16, 256)
    contam_kernel<<<grid, block>>>(x, out);
}